// round 13
// baseline (speedup 1.0000x reference)
#include <cuda_runtime.h>
#include <cstdint>

// Sparse dropout: out_values[i] = mask[i] ? values[i] * (1/KPROB) : 0
// KPROB = 0.5 -> scale = 2.0f
//
// Inputs (harness-marshaled):
//   d_in[0]: indices  int32, 2*NNZ elements
//   d_in[1]: values   float32, NNZ elements
//   d_in[2]: mask     int32 (0/1), NNZ elements
//
// Output (float32): [indices cast to f32 (2*NNZ)] ++ [dropout values (NNZ)]
// (falls back to values-only if out_size < 3*NNZ)
//
// R13: R8 config (fused launch, 16B vectors, MLP=2 idx / MLP=4 dropout,
// __ldcs/__stcs streaming — all individually verified) + Bresenham task
// interleaving: instead of [all idx blocks | all dropout blocks], every
// wave carries both tasks in global proportion, removing the intra-kernel
// phase boundary and keeping the DRAM read/write mix uniform in time.

static constexpr float SCALE = 2.0f;  // 1 / KPROB

__global__ void __launch_bounds__(256)
fused_sparse_dropout(const int4* __restrict__ idx,      // indices as int4
                     float4* __restrict__ out_idx,      // f32 indices out
                     int halfi,                         // idx int4-pairs per stride
                     int blocks_i,                      // blocks doing idx-cast
                     int blocks_total,
                     const float4* __restrict__ vals,
                     const int4* __restrict__ mask4,
                     float4* __restrict__ out_vals,
                     int halfv) {                       // value vec4-pairs per stride
    int b = blockIdx.x;
    // Bresenham interleave: among blocks [0, b) exactly floor(b*Bi/Bt) are
    // idx-cast blocks; block b is an idx-cast block iff the count advances.
    long long t = (long long)b * blocks_i;
    int before = (int)(t / blocks_total);
    int after  = (int)((t + blocks_i) / blocks_total);

    if (after > before) {
        // ---- index cast: 2 strided int4 -> float4 per thread (MLP=2) ----
        int i = before * blockDim.x + threadIdx.x;
        if (i < halfi) {
            int4 a0 = __ldcs(&idx[i]);
            int4 a1 = __ldcs(&idx[i + halfi]);
            __stcs(&out_idx[i],
                   make_float4((float)a0.x, (float)a0.y, (float)a0.z, (float)a0.w));
            __stcs(&out_idx[i + halfi],
                   make_float4((float)a1.x, (float)a1.y, (float)a1.z, (float)a1.w));
        }
    } else {
        // ---- dropout: 2 strided float4+int4 pairs per thread (MLP=4) ----
        int i = (b - before) * blockDim.x + threadIdx.x;
        if (i < halfv) {
            float4 v0 = __ldcs(&vals[i]);
            float4 v1 = __ldcs(&vals[i + halfv]);
            int4   m0 = __ldcs(&mask4[i]);
            int4   m1 = __ldcs(&mask4[i + halfv]);
            float4 o0, o1;
            o0.x = m0.x ? v0.x * SCALE : 0.0f;
            o0.y = m0.y ? v0.y * SCALE : 0.0f;
            o0.z = m0.z ? v0.z * SCALE : 0.0f;
            o0.w = m0.w ? v0.w * SCALE : 0.0f;
            o1.x = m1.x ? v1.x * SCALE : 0.0f;
            o1.y = m1.y ? v1.y * SCALE : 0.0f;
            o1.z = m1.z ? v1.z * SCALE : 0.0f;
            o1.w = m1.w ? v1.w * SCALE : 0.0f;
            __stcs(&out_vals[i], o0);
            __stcs(&out_vals[i + halfv], o1);
        }
    }
}

// Scalar tails (not expected to trigger: 64M and 32M are divisible by 8).
__global__ void __launch_bounds__(256)
idx_cast_tail(const int* __restrict__ idx, float* __restrict__ out,
              int start, int n) {
    int i = start + blockIdx.x * blockDim.x + threadIdx.x;
    if (i < n) out[i] = (float)idx[i];
}

__global__ void __launch_bounds__(256)
dropout_tail(const float* __restrict__ vals, const int* __restrict__ mask,
             float* __restrict__ out, int start, int n) {
    int i = start + blockIdx.x * blockDim.x + threadIdx.x;
    if (i < n) out[i] = mask[i] ? vals[i] * SCALE : 0.0f;
}

static inline int blocks_for(int n, int tpb) {
    return (int)(((long long)n + tpb - 1) / tpb);
}

extern "C" void kernel_launch(void* const* d_in, const int* in_sizes, int n_in,
                              void* d_out, int out_size) {
    const int*   indices = (const int*)d_in[0];
    const float* values  = (const float*)d_in[1];
    const int*   mask    = (const int*)d_in[2];

    const int n_idx = in_sizes[0];   // 2 * NNZ
    const int nnz   = in_sizes[1];   // NNZ

    const int TPB = 256;

    const bool combined = (out_size >= n_idx + nnz);
    float* out_idx    = (float*)d_out;
    float* out_values = combined ? ((float*)d_out + n_idx) : (float*)d_out;

    // Vectorized coverage
    int halfi = combined ? (n_idx / 4) / 2 : 0;   // int4 pairs for idx-cast
    int halfv = (nnz / 4) / 2;                    // vec4 pairs for dropout

    int blocks_i = halfi > 0 ? blocks_for(halfi, TPB) : 0;
    int blocks_d = halfv > 0 ? blocks_for(halfv, TPB) : 0;
    int blocks_total = blocks_i + blocks_d;

    if (blocks_total > 0) {
        fused_sparse_dropout<<<blocks_total, TPB>>>(
            (const int4*)indices, (float4*)out_idx, halfi, blocks_i, blocks_total,
            (const float4*)values, (const int4*)mask,
            (float4*)out_values, halfv);
    }

    // Tails (cover any elements beyond the vectorized region)
    if (combined) {
        int donei = halfi * 2 * 4;
        if (donei < n_idx) {
            idx_cast_tail<<<blocks_for(n_idx - donei, TPB), TPB>>>(
                indices, out_idx, donei, n_idx);
        }
    }
    int donev = halfv * 2 * 4;
    if (donev < nnz) {
        dropout_tail<<<blocks_for(nnz - donev, TPB), TPB>>>(
            values, mask, out_values, donev, nnz);
    }
}

// round 15
// speedup vs baseline: 1.0002x; 1.0002x over previous
#include <cuda_runtime.h>
#include <cstdint>

// Sparse dropout: out_values[i] = mask[i] ? values[i] * (1/KPROB) : 0
// KPROB = 0.5 -> scale = 2.0f
//
// Inputs (harness-marshaled):
//   d_in[0]: indices  int32, 2*NNZ elements
//   d_in[1]: values   float32, NNZ elements
//   d_in[2]: mask     int32 (0/1), NNZ elements
//
// Output (float32): [indices cast to f32 (2*NNZ)] ++ [dropout values (NNZ)]
// (falls back to values-only if out_size < 3*NNZ)
//
// R14 (resubmitted after infra failure): R13's task-interleaved fused
// kernel (best measured kernel time: 126.6us @ 6679 GB/s vs 127.4-128.5
// for sequential partitioning) with the block-mapping arithmetic
// specialized for the exact 2:1 idx:dropout block ratio (b%3 pattern)
// instead of generic 64-bit Bresenham. Bresenham kept as fallback for
// non-2:1 shapes. All other verified choices unchanged: single fused
// launch, 16B vectors, MLP=2 idx / MLP=4 dropout, __ldcs/__stcs streaming.

static constexpr float SCALE = 2.0f;  // 1 / KPROB

__global__ void __launch_bounds__(256)
fused_sparse_dropout(const int4* __restrict__ idx,      // indices as int4
                     float4* __restrict__ out_idx,      // f32 indices out
                     int halfi,                         // idx int4-pairs per stride
                     int blocks_i,                      // blocks doing idx-cast
                     int blocks_total,
                     int exact21,                       // 1 if blocks_i == 2*blocks_d
                     const float4* __restrict__ vals,
                     const int4* __restrict__ mask4,
                     float4* __restrict__ out_vals,
                     int halfv) {                       // value vec4-pairs per stride
    int b = blockIdx.x;

    int is_idx, task_b;
    if (exact21) {
        // Exact 2:1 interleave: blocks (3k, 3k+1) -> idx, (3k+2) -> dropout.
        int q = b / 3;
        int r = b - q * 3;
        is_idx = (r < 2);
        task_b = is_idx ? (q * 2 + r) : q;
    } else {
        // Generic Bresenham distribution of blocks_i idx blocks among
        // blocks_total blocks.
        long long t = (long long)b * blocks_i;
        int before = (int)(t / blocks_total);
        int after  = (int)((t + blocks_i) / blocks_total);
        is_idx = (after > before);
        task_b = is_idx ? before : (b - before);
    }

    if (is_idx) {
        // ---- index cast: 2 strided int4 -> float4 per thread (MLP=2) ----
        int i = task_b * blockDim.x + threadIdx.x;
        if (i < halfi) {
            int4 a0 = __ldcs(&idx[i]);
            int4 a1 = __ldcs(&idx[i + halfi]);
            __stcs(&out_idx[i],
                   make_float4((float)a0.x, (float)a0.y, (float)a0.z, (float)a0.w));
            __stcs(&out_idx[i + halfi],
                   make_float4((float)a1.x, (float)a1.y, (float)a1.z, (float)a1.w));
        }
    } else {
        // ---- dropout: 2 strided float4+int4 pairs per thread (MLP=4) ----
        int i = task_b * blockDim.x + threadIdx.x;
        if (i < halfv) {
            float4 v0 = __ldcs(&vals[i]);
            float4 v1 = __ldcs(&vals[i + halfv]);
            int4   m0 = __ldcs(&mask4[i]);
            int4   m1 = __ldcs(&mask4[i + halfv]);
            float4 o0, o1;
            o0.x = m0.x ? v0.x * SCALE : 0.0f;
            o0.y = m0.y ? v0.y * SCALE : 0.0f;
            o0.z = m0.z ? v0.z * SCALE : 0.0f;
            o0.w = m0.w ? v0.w * SCALE : 0.0f;
            o1.x = m1.x ? v1.x * SCALE : 0.0f;
            o1.y = m1.y ? v1.y * SCALE : 0.0f;
            o1.z = m1.z ? v1.z * SCALE : 0.0f;
            o1.w = m1.w ? v1.w * SCALE : 0.0f;
            __stcs(&out_vals[i], o0);
            __stcs(&out_vals[i + halfv], o1);
        }
    }
}

// Scalar tails (not expected to trigger: 64M and 32M are divisible by 8).
__global__ void __launch_bounds__(256)
idx_cast_tail(const int* __restrict__ idx, float* __restrict__ out,
              int start, int n) {
    int i = start + blockIdx.x * blockDim.x + threadIdx.x;
    if (i < n) out[i] = (float)idx[i];
}

__global__ void __launch_bounds__(256)
dropout_tail(const float* __restrict__ vals, const int* __restrict__ mask,
             float* __restrict__ out, int start, int n) {
    int i = start + blockIdx.x * blockDim.x + threadIdx.x;
    if (i < n) out[i] = mask[i] ? vals[i] * SCALE : 0.0f;
}

static inline int blocks_for(int n, int tpb) {
    return (int)(((long long)n + tpb - 1) / tpb);
}

extern "C" void kernel_launch(void* const* d_in, const int* in_sizes, int n_in,
                              void* d_out, int out_size) {
    const int*   indices = (const int*)d_in[0];
    const float* values  = (const float*)d_in[1];
    const int*   mask    = (const int*)d_in[2];

    const int n_idx = in_sizes[0];   // 2 * NNZ
    const int nnz   = in_sizes[1];   // NNZ

    const int TPB = 256;

    const bool combined = (out_size >= n_idx + nnz);
    float* out_idx    = (float*)d_out;
    float* out_values = combined ? ((float*)d_out + n_idx) : (float*)d_out;

    // Vectorized coverage
    int halfi = combined ? (n_idx / 4) / 2 : 0;   // int4 pairs for idx-cast
    int halfv = (nnz / 4) / 2;                    // vec4 pairs for dropout

    int blocks_i = halfi > 0 ? blocks_for(halfi, TPB) : 0;
    int blocks_d = halfv > 0 ? blocks_for(halfv, TPB) : 0;
    int blocks_total = blocks_i + blocks_d;
    int exact21 = (blocks_i == 2 * blocks_d) ? 1 : 0;

    if (blocks_total > 0) {
        fused_sparse_dropout<<<blocks_total, TPB>>>(
            (const int4*)indices, (float4*)out_idx, halfi, blocks_i,
            blocks_total, exact21,
            (const float4*)values, (const int4*)mask,
            (float4*)out_values, halfv);
    }

    // Tails (cover any elements beyond the vectorized region)
    if (combined) {
        int donei = halfi * 2 * 4;
        if (donei < n_idx) {
            idx_cast_tail<<<blocks_for(n_idx - donei, TPB), TPB>>>(
                indices, out_idx, donei, n_idx);
        }
    }
    int donev = halfv * 2 * 4;
    if (donev < nnz) {
        dropout_tail<<<blocks_for(nnz - donev, TPB), TPB>>>(
            values, mask, out_values, donev, nnz);
    }
}

// round 16
// speedup vs baseline: 1.0096x; 1.0093x over previous
#include <cuda_runtime.h>
#include <cstdint>

// Sparse dropout: out_values[i] = mask[i] ? values[i] * (1/KPROB) : 0
// KPROB = 0.5 -> scale = 2.0f
//
// Inputs (harness-marshaled):
//   d_in[0]: indices  int32, 2*NNZ elements
//   d_in[1]: values   float32, NNZ elements
//   d_in[2]: mask     int32 (0/1), NNZ elements
//
// Output (float32): [indices cast to f32 (2*NNZ)] ++ [dropout values (NNZ)]
// (falls back to values-only if out_size < 3*NNZ)
//
// FINAL — R8 config, verified best across three runs (133.8 / 134.7 /
// 134.7 us; kernel 127.4-128.5 us @ ~6.63 TB/s, DRAM ~81%).
// Experiment ledger (each single-variable, benched):
//  - 16B vector ld/st, 2 strided groups/thread (MLP=2 idx, MLP=4 dropout):
//    WIN over MLP=1/2 baseline (140.4 -> 136.3).
//  - __ldcs/__stcs streaming policy (896MB single-touch vs 126MB L2): WIN;
//    default-policy stores regressed (R9: 136.2).
//  - Single fused launch, block-partitioned idx-cast|dropout: WIN
//    (136.3 -> 133.8; kills the inter-kernel ramp bubble).
//  - Deeper batching MLP=8/4 (R11): REGRESSION (137.0) — L1tex queue
//    contention, no BW gain.
//  - Bresenham/2:1 task interleaving (R13/R15): totals 135.1-135.2,
//    consistently above all R8 runs — reverted.
// The chip's sustained LTS/HBM cap (~6.6 TB/s) binds; the 896 MB of
// traffic is mandatory (idx bits must be rewritten as f32, mask arrives as
// 4B int32). This is the practical floor.

static constexpr float SCALE = 2.0f;  // 1 / KPROB

__global__ void __launch_bounds__(256)
fused_sparse_dropout(const int4* __restrict__ idx,      // indices as int4
                     float4* __restrict__ out_idx,      // f32 indices out
                     int halfi,                         // idx int4-pairs per stride
                     int blocks_i,                      // blocks assigned to idx-cast
                     const float4* __restrict__ vals,
                     const int4* __restrict__ mask4,
                     float4* __restrict__ out_vals,
                     int halfv) {                       // value vec4-pairs per stride
    int b = blockIdx.x;
    if (b < blocks_i) {
        // ---- index cast: 2 strided int4 -> float4 per thread (MLP=2) ----
        int i = b * blockDim.x + threadIdx.x;
        if (i < halfi) {
            int4 a0 = __ldcs(&idx[i]);
            int4 a1 = __ldcs(&idx[i + halfi]);
            __stcs(&out_idx[i],
                   make_float4((float)a0.x, (float)a0.y, (float)a0.z, (float)a0.w));
            __stcs(&out_idx[i + halfi],
                   make_float4((float)a1.x, (float)a1.y, (float)a1.z, (float)a1.w));
        }
    } else {
        // ---- dropout: 2 strided float4+int4 pairs per thread (MLP=4) ----
        int i = (b - blocks_i) * blockDim.x + threadIdx.x;
        if (i < halfv) {
            float4 v0 = __ldcs(&vals[i]);
            float4 v1 = __ldcs(&vals[i + halfv]);
            int4   m0 = __ldcs(&mask4[i]);
            int4   m1 = __ldcs(&mask4[i + halfv]);
            float4 o0, o1;
            o0.x = m0.x ? v0.x * SCALE : 0.0f;
            o0.y = m0.y ? v0.y * SCALE : 0.0f;
            o0.z = m0.z ? v0.z * SCALE : 0.0f;
            o0.w = m0.w ? v0.w * SCALE : 0.0f;
            o1.x = m1.x ? v1.x * SCALE : 0.0f;
            o1.y = m1.y ? v1.y * SCALE : 0.0f;
            o1.z = m1.z ? v1.z * SCALE : 0.0f;
            o1.w = m1.w ? v1.w * SCALE : 0.0f;
            __stcs(&out_vals[i], o0);
            __stcs(&out_vals[i + halfv], o1);
        }
    }
}

// Scalar tails (not expected to trigger: 64M and 32M are divisible by 8).
__global__ void __launch_bounds__(256)
idx_cast_tail(const int* __restrict__ idx, float* __restrict__ out,
              int start, int n) {
    int i = start + blockIdx.x * blockDim.x + threadIdx.x;
    if (i < n) out[i] = (float)idx[i];
}

__global__ void __launch_bounds__(256)
dropout_tail(const float* __restrict__ vals, const int* __restrict__ mask,
             float* __restrict__ out, int start, int n) {
    int i = start + blockIdx.x * blockDim.x + threadIdx.x;
    if (i < n) out[i] = mask[i] ? vals[i] * SCALE : 0.0f;
}

static inline int blocks_for(int n, int tpb) {
    return (int)(((long long)n + tpb - 1) / tpb);
}

extern "C" void kernel_launch(void* const* d_in, const int* in_sizes, int n_in,
                              void* d_out, int out_size) {
    const int*   indices = (const int*)d_in[0];
    const float* values  = (const float*)d_in[1];
    const int*   mask    = (const int*)d_in[2];

    const int n_idx = in_sizes[0];   // 2 * NNZ
    const int nnz   = in_sizes[1];   // NNZ

    const int TPB = 256;

    const bool combined = (out_size >= n_idx + nnz);
    float* out_idx    = (float*)d_out;
    float* out_values = combined ? ((float*)d_out + n_idx) : (float*)d_out;

    // Vectorized coverage
    int halfi = combined ? (n_idx / 4) / 2 : 0;   // int4 pairs for idx-cast
    int halfv = (nnz / 4) / 2;                    // vec4 pairs for dropout

    int blocks_i = halfi > 0 ? blocks_for(halfi, TPB) : 0;
    int blocks_d = halfv > 0 ? blocks_for(halfv, TPB) : 0;

    if (blocks_i + blocks_d > 0) {
        fused_sparse_dropout<<<blocks_i + blocks_d, TPB>>>(
            (const int4*)indices, (float4*)out_idx, halfi, blocks_i,
            (const float4*)values, (const int4*)mask,
            (float4*)out_values, halfv);
    }

    // Tails (cover any elements beyond the vectorized region)
    if (combined) {
        int donei = halfi * 2 * 4;
        if (donei < n_idx) {
            idx_cast_tail<<<blocks_for(n_idx - donei, TPB), TPB>>>(
                indices, out_idx, donei, n_idx);
        }
    }
    int donev = halfv * 2 * 4;
    if (donev < nnz) {
        dropout_tail<<<blocks_for(nnz - donev, TPB), TPB>>>(
            values, mask, out_values, donev, nnz);
    }
}